// round 12
// baseline (speedup 1.0000x reference)
#include <cuda_runtime.h>

#define Bv 8
#define Cv 128
#define Hv 128
#define Wv 128
#define KK 9
#define NPLANES (Bv * Cv)
#define CONV_CTAS 592   /* 148 SMs x 4 resident */

// Scratch (no allocations allowed in kernel_launch)
__device__ float g_pooled[Bv * Cv];
__device__ float g_h[Bv * Cv];
__device__ unsigned int g_ctr;
__device__ unsigned int g_done[Bv];
__device__ volatile unsigned int g_hdone[Bv];

// ---------------------------------------------------------------------------
// Kernel 0: reset pipeline state (graph replays need fresh state every call).
// ---------------------------------------------------------------------------
__global__ void init_kernel() {
    if (threadIdx.x < Bv) {
        g_done[threadIdx.x] = 0;
        g_hdone[threadIdx.x] = 0;
    }
    if (threadIdx.x == 0) g_ctr = 0;
}

// ---------------------------------------------------------------------------
// Item schedule (2048 items) interleaving pool reads and conv writes:
//   [0,128)        : pool  b=0, plane=item
//   [128,1920)     : block g=(item-128)/256, r=(item-128)%256, c=r>>1
//                    r even -> conv plane g*128+c ; r odd -> pool plane (g+1)*128+c
//   [1920,2048)    : conv  b=7, plane=896+(item-1920)
// Guarantees: every pool(b) item precedes every conv(b) item in counter order.
// ---------------------------------------------------------------------------
__device__ __forceinline__ void decode_item(unsigned item, int& is_conv, int& plane) {
    if (item < 128u) {
        is_conv = 0; plane = item;
    } else if (item < 1920u) {
        const unsigned t = item - 128u;
        const unsigned g = t >> 8;          // 0..6
        const unsigned r = t & 255u;
        const unsigned c = r >> 1;
        if ((r & 1u) == 0u) { is_conv = 1; plane = g * 128u + c; }
        else                { is_conv = 0; plane = (g + 1u) * 128u + c; }
    } else {
        is_conv = 1; plane = 896u + (item - 1920u);
    }
}

// ---------------------------------------------------------------------------
// Kernel 1: persistent pipelined pool -> h -> kern+conv, interleaved schedule.
// Conv: scalar FMA, 6-float register rows, 4-row batched loads (MLP=4).
// ---------------------------------------------------------------------------
__global__ void __launch_bounds__(256, 4)
mega_kernel(const float* __restrict__ x,
            const float* __restrict__ w1, const float* __restrict__ b1,
            const float* __restrict__ w2, const float* __restrict__ b2,
            float* __restrict__ out) {
    const int tid = threadIdx.x;
    const int wid = tid >> 5;       // 0..7
    const int lane = tid & 31;

    __shared__ unsigned int s_item;
    __shared__ int s_do_h;
    __shared__ float sdata[8];
    __shared__ float kw[KK];

    for (;;) {
        if (tid == 0) s_item = atomicAdd(&g_ctr, 1u);
        __syncthreads();
        const unsigned int item = s_item;
        if (item >= 2u * NPLANES) break;

        int is_conv, plane;
        decode_item(item, is_conv, plane);
        const int b = plane >> 7;
        const int c = plane & 127;

        if (!is_conv) {
            // ================= POOL (+ maybe h) =================
            const float4* xp = (const float4*)(x + (size_t)plane * Hv * Wv);

            float sum = 0.f;
#pragma unroll
            for (int i = 0; i < 16; i++) {
                float4 v = xp[tid + i * 256];
                sum += (v.x + v.y) + (v.z + v.w);
            }
#pragma unroll
            for (int o = 16; o; o >>= 1) sum += __shfl_down_sync(0xffffffffu, sum, o);
            if (lane == 0) sdata[wid] = sum;
            __syncthreads();
            if (tid == 0) {
                float t = sdata[0];
#pragma unroll
                for (int i = 1; i < 8; i++) t += sdata[i];
                g_pooled[plane] = t * (1.f / (float)(Hv * Wv));
                __threadfence();
                const unsigned int d = atomicAdd(&g_done[b], 1u);
                s_do_h = (d == Cv - 1);
            }
            __syncthreads();

            if (s_do_h) {
                __threadfence();  // observe all 128 pooled writes
                const float4 pv = __ldcg((const float4*)(g_pooled + b * Cv) + lane);
#pragma unroll 4
                for (int i = 0; i < 16; i++) {
                    const int o = wid * 16 + i;
                    const float4 wv = __ldg((const float4*)(w1 + (size_t)o * Cv) + lane);
                    float acc = wv.x * pv.x;
                    acc = fmaf(wv.y, pv.y, acc);
                    acc = fmaf(wv.z, pv.z, acc);
                    acc = fmaf(wv.w, pv.w, acc);
#pragma unroll
                    for (int s = 16; s; s >>= 1) acc += __shfl_xor_sync(0xffffffffu, acc, s);
                    if (lane == 0) g_h[b * Cv + o] = fmaxf(acc + b1[o], 0.f);
                }
                __syncthreads();
                if (tid == 0) {
                    __threadfence();
                    g_hdone[b] = 1u;   // release flag
                }
            }
        } else {
            // ================= KERN TAPS + CONV =================
            if (tid == 0) {
                while (g_hdone[b] == 0u) __nanosleep(64);
            }
            __syncthreads();
            __threadfence();  // acquire before g_h reads

            {
                const float4 hv = __ldcg((const float4*)(g_h + b * Cv) + lane);
#pragma unroll
                for (int rep = 0; rep < 2; rep++) {
                    const int p = wid + rep * 8;
                    if (p < KK) {
                        const float4 wv = __ldg((const float4*)(w2 + (size_t)(c * KK + p) * Cv) + lane);
                        float acc = wv.x * hv.x;
                        acc = fmaf(wv.y, hv.y, acc);
                        acc = fmaf(wv.z, hv.z, acc);
                        acc = fmaf(wv.w, hv.w, acc);
#pragma unroll
                        for (int s = 16; s; s >>= 1) acc += __shfl_xor_sync(0xffffffffu, acc, s);
                        if (lane == 0) kw[p] = acc + b2[c * KK + p];
                    }
                }
            }
            __syncthreads();

            float w[9];
#pragma unroll
            for (int p = 0; p < 9; p++) w[p] = kw[p];

            const int row0 = wid * 16;
            const float* xp = x + (size_t)plane * Hv * Wv;
            float* op = out + (size_t)plane * Hv * Wv;

#define LOADF4(v, gr)                                                         \
            {                                                                 \
                if ((gr) < 0 || (gr) >= Hv) { v.x = v.y = v.z = v.w = 0.f; }  \
                else v = __ldg((const float4*)(xp + (gr) * Wv) + lane);       \
            }
#define CONVROW(a, v)                                                         \
            {                                                                 \
                float cm1 = __shfl_up_sync(0xffffffffu, v.w, 1);              \
                float cp4 = __shfl_down_sync(0xffffffffu, v.x, 1);            \
                if (lane == 0) cm1 = 0.f;                                     \
                if (lane == 31) cp4 = 0.f;                                    \
                a[0] = cm1; a[1] = v.x; a[2] = v.y;                           \
                a[3] = v.z; a[4] = v.w; a[5] = cp4;                           \
            }
#define OUTROW(gr, X, Y, Z)                                                   \
            {                                                                 \
                float4 o;                                                     \
                float* po = &o.x;                                             \
                _Pragma("unroll")                                             \
                for (int k = 0; k < 4; k++) {                                 \
                    float acc = X[k] * w[0];                                  \
                    acc = fmaf(X[k + 1], w[1], acc);                          \
                    acc = fmaf(X[k + 2], w[2], acc);                          \
                    acc = fmaf(Y[k],     w[3], acc);                          \
                    acc = fmaf(Y[k + 1], w[4], acc);                          \
                    acc = fmaf(Y[k + 2], w[5], acc);                          \
                    acc = fmaf(Z[k],     w[6], acc);                          \
                    acc = fmaf(Z[k + 1], w[7], acc);                          \
                    acc = fmaf(Z[k + 2], w[8], acc);                          \
                    po[k] = acc;                                              \
                }                                                             \
                __stcs((float4*)(op + (gr) * Wv) + lane, o);                  \
            }

            float A[6], B[6], C[6], D[6], E[6], F[6];
            {
                float4 v;
                LOADF4(v, row0 - 1); CONVROW(A, v);
                LOADF4(v, row0);     CONVROW(B, v);
            }

#pragma unroll
            for (int ch = 0; ch < 4; ch++) {
                const int obase = row0 + ch * 4;
                float4 p0, p1, p2, p3;
                LOADF4(p0, obase + 1);
                LOADF4(p1, obase + 2);
                LOADF4(p2, obase + 3);
                LOADF4(p3, obase + 4);
                CONVROW(C, p0);
                CONVROW(D, p1);
                CONVROW(E, p2);
                CONVROW(F, p3);

                OUTROW(obase + 0, A, B, C);
                OUTROW(obase + 1, B, C, D);
                OUTROW(obase + 2, C, D, E);
                OUTROW(obase + 3, D, E, F);

#pragma unroll
                for (int q = 0; q < 6; q++) { A[q] = E[q]; B[q] = F[q]; }
            }
#undef LOADF4
#undef CONVROW
#undef OUTROW
        }
    }
}

// ---------------------------------------------------------------------------
extern "C" void kernel_launch(void* const* d_in, const int* in_sizes, int n_in,
                              void* d_out, int out_size) {
    const float* x  = (const float*)d_in[0];
    const float* w1 = (const float*)d_in[1];
    const float* b1 = (const float*)d_in[2];
    const float* w2 = (const float*)d_in[3];
    const float* b2 = (const float*)d_in[4];
    float* out = (float*)d_out;

    init_kernel<<<1, 32>>>();
    mega_kernel<<<CONV_CTAS, 256>>>(x, w1, b1, w2, b2, out);
}

// round 13
// speedup vs baseline: 1.2226x; 1.2226x over previous
#include <cuda_runtime.h>

#define Bv 8
#define Cv 128
#define Hv 128
#define Wv 128
#define KK 9
#define NPLANES (Bv * Cv)
#define CONV_CTAS 592   /* 148 SMs x 4 resident */

// Scratch (no allocations allowed in kernel_launch).
// Zero-initialized at module load; self-reset by the exit protocol thereafter.
__device__ float g_pooled[Bv * Cv];
__device__ float g_h[Bv * Cv];
__device__ unsigned int g_ctr;
__device__ unsigned int g_exit;
__device__ unsigned int g_done[Bv];
__device__ volatile unsigned int g_hdone[Bv];

// ---------------------------------------------------------------------------
// Persistent pipelined pool -> h -> kern+conv (batch-major: all pool items
// precede all conv items; sequential read phase then write phase, which R12
// showed is what HBM wants).
// Self-resetting: the last CTA to exit restores all state for the next replay.
// ---------------------------------------------------------------------------
__global__ void __launch_bounds__(256, 4)
mega_kernel(const float* __restrict__ x,
            const float* __restrict__ w1, const float* __restrict__ b1,
            const float* __restrict__ w2, const float* __restrict__ b2,
            float* __restrict__ out) {
    const int tid = threadIdx.x;
    const int wid = tid >> 5;       // 0..7
    const int lane = tid & 31;

    __shared__ unsigned int s_item;
    __shared__ int s_do_h;
    __shared__ float sdata[8];
    __shared__ float kw[KK];

    for (;;) {
        if (tid == 0) s_item = atomicAdd(&g_ctr, 1u);
        __syncthreads();
        const unsigned int item = s_item;
        if (item >= 2u * NPLANES) break;

        if (item < NPLANES) {
            // ================= POOL (+ maybe h) =================
            const int plane = item;
            const int b = plane >> 7;
            const float4* xp = (const float4*)(x + (size_t)plane * Hv * Wv);

            float sum = 0.f;
#pragma unroll
            for (int i = 0; i < 16; i++) {
                float4 v = xp[tid + i * 256];
                sum += (v.x + v.y) + (v.z + v.w);
            }
#pragma unroll
            for (int o = 16; o; o >>= 1) sum += __shfl_down_sync(0xffffffffu, sum, o);
            if (lane == 0) sdata[wid] = sum;
            __syncthreads();
            if (tid == 0) {
                float t = sdata[0];
#pragma unroll
                for (int i = 1; i < 8; i++) t += sdata[i];
                g_pooled[plane] = t * (1.f / (float)(Hv * Wv));
                __threadfence();
                const unsigned int d = atomicAdd(&g_done[b], 1u);
                s_do_h = (d == Cv - 1);
            }
            __syncthreads();

            if (s_do_h) {
                __threadfence();  // observe all 128 pooled writes
                const float4 pv = __ldcg((const float4*)(g_pooled + b * Cv) + lane);
#pragma unroll 4
                for (int i = 0; i < 16; i++) {
                    const int o = wid * 16 + i;
                    const float4 wv = __ldg((const float4*)(w1 + (size_t)o * Cv) + lane);
                    float acc = wv.x * pv.x;
                    acc = fmaf(wv.y, pv.y, acc);
                    acc = fmaf(wv.z, pv.z, acc);
                    acc = fmaf(wv.w, pv.w, acc);
#pragma unroll
                    for (int s = 16; s; s >>= 1) acc += __shfl_xor_sync(0xffffffffu, acc, s);
                    if (lane == 0) g_h[b * Cv + o] = fmaxf(acc + b1[o], 0.f);
                }
                __syncthreads();
                if (tid == 0) {
                    __threadfence();
                    g_hdone[b] = 1u;   // release flag
                }
            }
        } else {
            // ================= KERN TAPS + CONV =================
            const int plane = item - NPLANES;
            const int b = plane >> 7;
            const int c = plane & 127;

            if (tid == 0) {
                while (g_hdone[b] == 0u) __nanosleep(64);
            }
            __syncthreads();
            __threadfence();  // acquire before g_h reads

            {
                const float4 hv = __ldcg((const float4*)(g_h + b * Cv) + lane);
#pragma unroll
                for (int rep = 0; rep < 2; rep++) {
                    const int p = wid + rep * 8;
                    if (p < KK) {
                        const float4 wv = __ldg((const float4*)(w2 + (size_t)(c * KK + p) * Cv) + lane);
                        float acc = wv.x * hv.x;
                        acc = fmaf(wv.y, hv.y, acc);
                        acc = fmaf(wv.z, hv.z, acc);
                        acc = fmaf(wv.w, hv.w, acc);
#pragma unroll
                        for (int s = 16; s; s >>= 1) acc += __shfl_xor_sync(0xffffffffu, acc, s);
                        if (lane == 0) kw[p] = acc + b2[c * KK + p];
                    }
                }
            }
            __syncthreads();

            float w[9];
#pragma unroll
            for (int p = 0; p < 9; p++) w[p] = kw[p];

            const int row0 = wid * 16;
            const float* xp = x + (size_t)plane * Hv * Wv;
            float* op = out + (size_t)plane * Hv * Wv;

#define LOADF4(v, gr)                                                         \
            {                                                                 \
                if ((gr) < 0 || (gr) >= Hv) { v.x = v.y = v.z = v.w = 0.f; }  \
                else v = __ldg((const float4*)(xp + (gr) * Wv) + lane);       \
            }
#define CONVROW(a, v)                                                         \
            {                                                                 \
                float cm1 = __shfl_up_sync(0xffffffffu, v.w, 1);              \
                float cp4 = __shfl_down_sync(0xffffffffu, v.x, 1);            \
                if (lane == 0) cm1 = 0.f;                                     \
                if (lane == 31) cp4 = 0.f;                                    \
                a[0] = cm1; a[1] = v.x; a[2] = v.y;                           \
                a[3] = v.z; a[4] = v.w; a[5] = cp4;                           \
            }
#define OUTROW(gr, X, Y, Z)                                                   \
            {                                                                 \
                float4 o;                                                     \
                float* po = &o.x;                                             \
                _Pragma("unroll")                                             \
                for (int k = 0; k < 4; k++) {                                 \
                    float acc = X[k] * w[0];                                  \
                    acc = fmaf(X[k + 1], w[1], acc);                          \
                    acc = fmaf(X[k + 2], w[2], acc);                          \
                    acc = fmaf(Y[k],     w[3], acc);                          \
                    acc = fmaf(Y[k + 1], w[4], acc);                          \
                    acc = fmaf(Y[k + 2], w[5], acc);                          \
                    acc = fmaf(Z[k],     w[6], acc);                          \
                    acc = fmaf(Z[k + 1], w[7], acc);                          \
                    acc = fmaf(Z[k + 2], w[8], acc);                          \
                    po[k] = acc;                                              \
                }                                                             \
                __stcs((float4*)(op + (gr) * Wv) + lane, o);                  \
            }

            float A[6], B[6], C[6], D[6], E[6], F[6];
            {
                float4 v;
                LOADF4(v, row0 - 1); CONVROW(A, v);
                LOADF4(v, row0);     CONVROW(B, v);
            }

#pragma unroll
            for (int ch = 0; ch < 4; ch++) {
                const int obase = row0 + ch * 4;
                float4 p0, p1, p2, p3;
                LOADF4(p0, obase + 1);
                LOADF4(p1, obase + 2);
                LOADF4(p2, obase + 3);
                LOADF4(p3, obase + 4);
                CONVROW(C, p0);
                CONVROW(D, p1);
                CONVROW(E, p2);
                CONVROW(F, p3);

                OUTROW(obase + 0, A, B, C);
                OUTROW(obase + 1, B, C, D);
                OUTROW(obase + 2, C, D, E);
                OUTROW(obase + 3, D, E, F);

#pragma unroll
                for (int q = 0; q < 6; q++) { A[q] = E[q]; B[q] = F[q]; }
            }
#undef LOADF4
#undef CONVROW
#undef OUTROW
        }
    }

    // ---- exit protocol: last CTA out resets all state for the next replay ----
    __syncthreads();
    if (tid == 0) {
        const unsigned int prev = atomicAdd(&g_exit, 1u);
        if (prev == (unsigned)(gridDim.x - 1)) {
#pragma unroll
            for (int i = 0; i < Bv; i++) {
                g_done[i] = 0;
                g_hdone[i] = 0;
            }
            g_ctr = 0;
            __threadfence();
            g_exit = 0;
        }
    }
}

// ---------------------------------------------------------------------------
extern "C" void kernel_launch(void* const* d_in, const int* in_sizes, int n_in,
                              void* d_out, int out_size) {
    const float* x  = (const float*)d_in[0];
    const float* w1 = (const float*)d_in[1];
    const float* b1 = (const float*)d_in[2];
    const float* w2 = (const float*)d_in[3];
    const float* b2 = (const float*)d_in[4];
    float* out = (float*)d_out;

    mega_kernel<<<CONV_CTAS, 256>>>(x, w1, b1, w2, b2, out);
}